// round 2
// baseline (speedup 1.0000x reference)
#include <cuda_runtime.h>

#define N_TOK 4096
#define CDIM  256
#define NHEAD 8
#define HDIM  32

// ---- scratch (static __device__ arrays; no allocation allowed) ----
__device__ float g_xn [2 * N_TOK * CDIM];        // (B,N,C) layernormed
__device__ float g_qkv[2 * N_TOK * 3 * CDIM];    // (B,N,768)
__device__ float g_att[2 * N_TOK * CDIM];        // (B,N,C) attention out

__device__ __forceinline__ float ex2f(float x) {
    float y; asm("ex2.approx.ftz.f32 %0, %1;" : "=f"(y) : "f"(x)); return y;
}

// ---------------- Kernel 1: LayerNorm + (B,C,N)->(B,N,C) transpose ----------
__global__ __launch_bounds__(256) void ln_kernel(
    const float* __restrict__ x, const float* __restrict__ nw,
    const float* __restrict__ nb)
{
    __shared__ float ts[CDIM][33];
    int tid = threadIdx.x;
    int b  = blockIdx.x >> 7;
    int n0 = (blockIdx.x & 127) * 32;

    int j = tid & 31;
    for (int c = tid >> 5; c < CDIM; c += 8)
        ts[c][j] = x[(size_t)(b * CDIM + c) * N_TOK + n0 + j];
    __syncthreads();

    int jt = tid >> 3, g = tid & 7;
    float sum = 0.f, sq = 0.f;
    #pragma unroll
    for (int c0 = 0; c0 < CDIM; c0 += 8) {
        float v = ts[c0 + g][jt];
        sum += v; sq += v * v;
    }
    #pragma unroll
    for (int mm = 1; mm < 8; mm <<= 1) {
        sum += __shfl_xor_sync(0xffffffffu, sum, mm);
        sq  += __shfl_xor_sync(0xffffffffu, sq,  mm);
    }
    float mean = sum * (1.f / CDIM);
    float var  = sq  * (1.f / CDIM) - mean * mean;
    float rstd = rsqrtf(var + 1e-5f);

    float* orow = g_xn + (size_t)(b * N_TOK + n0 + jt) * CDIM;
    #pragma unroll
    for (int i = 0; i < 8; i++) {
        int c = g * 32 + i * 4;
        float4 w4 = *(const float4*)(nw + c);
        float4 b4 = *(const float4*)(nb + c);
        float4 o;
        o.x = (ts[c + 0][jt] - mean) * rstd * w4.x + b4.x;
        o.y = (ts[c + 1][jt] - mean) * rstd * w4.y + b4.y;
        o.z = (ts[c + 2][jt] - mean) * rstd * w4.z + b4.z;
        o.w = (ts[c + 3][jt] - mean) * rstd * w4.w + b4.w;
        *(float4*)(orow + c) = o;
    }
}

// ---------------- Kernel 2: QKV GEMM (8192x768x256) + bias -----------------
__global__ __launch_bounds__(256) void qkv_gemm_kernel(
    const float* __restrict__ W, const float* __restrict__ bias)
{
    __shared__ float As[32][65];
    __shared__ float Bs[32][65];
    int tid = threadIdx.x;
    int m0 = blockIdx.x * 64;
    int j0 = blockIdx.y * 64;
    int ty = tid >> 4, tx = tid & 15;
    float c[4][4] = {};

    for (int kc = 0; kc < 256; kc += 32) {
        for (int idx = tid; idx < 2048; idx += 256) {
            int r = idx >> 5, k = idx & 31;
            As[k][r] = g_xn[(size_t)(m0 + r) * 256 + kc + k];
            Bs[k][r] = W[(size_t)(j0 + r) * 256 + kc + k];
        }
        __syncthreads();
        #pragma unroll
        for (int k = 0; k < 32; k++) {
            float a[4], bb[4];
            #pragma unroll
            for (int i = 0; i < 4; i++) a[i]  = As[k][ty * 4 + i];
            #pragma unroll
            for (int jj = 0; jj < 4; jj++) bb[jj] = Bs[k][tx * 4 + jj];
            #pragma unroll
            for (int i = 0; i < 4; i++)
                #pragma unroll
                for (int jj = 0; jj < 4; jj++)
                    c[i][jj] += a[i] * bb[jj];
        }
        __syncthreads();
    }
    float4 b4 = *(const float4*)(bias + j0 + tx * 4);
    #pragma unroll
    for (int i = 0; i < 4; i++) {
        float4 o = { c[i][0] + b4.x, c[i][1] + b4.y, c[i][2] + b4.z, c[i][3] + b4.w };
        *(float4*)(g_qkv + (size_t)(m0 + ty * 4 + i) * 768 + j0 + tx * 4) = o;
    }
}

// ---------------- Kernel 3: flash attention ---------------------------------
struct AttnSmem {
    float Qs[128][32];     // pre-scaled by scale*log2(e)
    float Kt[32][68];      // K transposed, padded
    float Vs[64][32];
    float Ps[128][65];     // P tile, padded
    float row_m[128];
    float row_l[128];
    float row_c[128];
};
#define ATTN_SMEM_BYTES (sizeof(AttnSmem))

__global__ __launch_bounds__(256) void attn_kernel()
{
    extern __shared__ char smem_raw[];
    AttnSmem& s = *reinterpret_cast<AttnSmem*>(smem_raw);
    int tid = threadIdx.x;
    int bid = blockIdx.x;
    int b  = bid >> 8;
    int h  = (bid >> 5) & 7;
    int q0 = (bid & 31) * 128;
    const float qscale = 0.17677669529663689f * 1.4426950408889634f; // 1/sqrt(32)*log2e
    const float* qb = g_qkv + (size_t)b * N_TOK * 768;

    for (int idx = tid; idx < 128 * 32; idx += 256) {
        int r = idx >> 5, d = idx & 31;
        s.Qs[r][d] = qb[(size_t)(q0 + r) * 768 + h * 32 + d] * qscale;
    }
    if (tid < 128) { s.row_m[tid] = -1e30f; s.row_l[tid] = 0.f; }

    int ty = tid >> 4, tx = tid & 15;
    int r0 = ty * 8, c0 = tx * 4;          // S-phase: 8 rows x 4 cols per thread
    int rp = tid >> 3, dg = tid & 7;
    int rr0 = rp * 4, dd0 = dg * 4;        // PV-phase: 4 rows x 4 dims per thread
    float acc[4][4] = {};
    __syncthreads();

    for (int kt = 0; kt < 64; kt++) {
        int k0 = kt * 64;
        for (int idx = tid; idx < 64 * 32; idx += 256) {
            int r = idx >> 5, d = idx & 31;
            const float* p = qb + (size_t)(k0 + r) * 768 + h * 32 + d;
            s.Kt[d][r] = p[256];
            s.Vs[r][d] = p[512];
        }
        __syncthreads();

        // ---- S = Q K^T tile ----
        float sc[8][4];
        #pragma unroll
        for (int i = 0; i < 8; i++) sc[i][0] = sc[i][1] = sc[i][2] = sc[i][3] = 0.f;
        #pragma unroll 4
        for (int d = 0; d < 32; d++) {
            float4 kk = *(const float4*)&s.Kt[d][c0];
            #pragma unroll
            for (int i = 0; i < 8; i++) {
                float q = s.Qs[r0 + i][d];
                sc[i][0] += q * kk.x;
                sc[i][1] += q * kk.y;
                sc[i][2] += q * kk.z;
                sc[i][3] += q * kk.w;
            }
        }

        // ---- online softmax (base-2 domain) ----
        #pragma unroll
        for (int i = 0; i < 8; i++) {
            int r = r0 + i;
            float tmax = fmaxf(fmaxf(sc[i][0], sc[i][1]), fmaxf(sc[i][2], sc[i][3]));
            #pragma unroll
            for (int mm = 1; mm < 16; mm <<= 1)
                tmax = fmaxf(tmax, __shfl_xor_sync(0xffffffffu, tmax, mm));
            float m_old = s.row_m[r];
            float m_new = fmaxf(m_old, tmax);
            float p0 = ex2f(sc[i][0] - m_new);
            float p1 = ex2f(sc[i][1] - m_new);
            float p2 = ex2f(sc[i][2] - m_new);
            float p3 = ex2f(sc[i][3] - m_new);
            float rs = (p0 + p1) + (p2 + p3);
            #pragma unroll
            for (int mm = 1; mm < 16; mm <<= 1)
                rs += __shfl_xor_sync(0xffffffffu, rs, mm);
            if (tx == 0) {
                float cf = ex2f(m_old - m_new);
                s.row_c[r] = cf;
                s.row_l[r] = s.row_l[r] * cf + rs;
                s.row_m[r] = m_new;
            }
            s.Ps[r][c0 + 0] = p0;
            s.Ps[r][c0 + 1] = p1;
            s.Ps[r][c0 + 2] = p2;
            s.Ps[r][c0 + 3] = p3;
        }
        __syncthreads();

        // ---- O = O*corr + P V ----
        float cf[4];
        #pragma unroll
        for (int i = 0; i < 4; i++) cf[i] = s.row_c[rr0 + i];
        #pragma unroll
        for (int i = 0; i < 4; i++)
            #pragma unroll
            for (int jj = 0; jj < 4; jj++) acc[i][jj] *= cf[i];
        #pragma unroll 2
        for (int kx = 0; kx < 64; kx++) {
            float4 vv = *(const float4*)&s.Vs[kx][dd0];
            #pragma unroll
            for (int i = 0; i < 4; i++) {
                float p = s.Ps[rr0 + i][kx];
                acc[i][0] += p * vv.x;
                acc[i][1] += p * vv.y;
                acc[i][2] += p * vv.z;
                acc[i][3] += p * vv.w;
            }
        }
        __syncthreads();
    }

    #pragma unroll
    for (int i = 0; i < 4; i++) {
        int r = rr0 + i;
        float inv = 1.0f / s.row_l[r];
        float4 o = { acc[i][0] * inv, acc[i][1] * inv, acc[i][2] * inv, acc[i][3] * inv };
        *(float4*)(g_att + (size_t)(b * N_TOK + q0 + r) * 256 + h * 32 + dd0) = o;
    }
}

// ---------------- Kernel 4: proj GEMM + gamma residual ----------------------
__global__ __launch_bounds__(256) void proj_kernel(
    const float* __restrict__ W, const float* __restrict__ bias,
    const float* __restrict__ gamma, const float* __restrict__ x,
    float* __restrict__ out)
{
    __shared__ float sm[4160];
    float (*As)[65] = (float(*)[65])sm;
    float (*Bs)[65] = (float(*)[65])(sm + 2080);
    int tid = threadIdx.x;
    int m0 = blockIdx.x * 64;
    int j0 = blockIdx.y * 64;
    int ty = tid >> 4, tx = tid & 15;
    float c[4][4] = {};

    for (int kc = 0; kc < 256; kc += 32) {
        for (int idx = tid; idx < 2048; idx += 256) {
            int r = idx >> 5, k = idx & 31;
            As[k][r] = g_att[(size_t)(m0 + r) * 256 + kc + k];
            Bs[k][r] = W[(size_t)(j0 + r) * 256 + kc + k];
        }
        __syncthreads();
        #pragma unroll
        for (int k = 0; k < 32; k++) {
            float a[4], bb[4];
            #pragma unroll
            for (int i = 0; i < 4; i++) a[i]  = As[k][ty * 4 + i];
            #pragma unroll
            for (int jj = 0; jj < 4; jj++) bb[jj] = Bs[k][tx * 4 + jj];
            #pragma unroll
            for (int i = 0; i < 4; i++)
                #pragma unroll
                for (int jj = 0; jj < 4; jj++)
                    c[i][jj] += a[i] * bb[jj];
        }
        __syncthreads();
    }

    // stage C tile transposed in smem for coalesced (C,N)-layout writes
    float (*Cs)[65] = (float(*)[65])sm;
    float4 b4 = *(const float4*)(bias + j0 + tx * 4);
    float pb[4] = { b4.x, b4.y, b4.z, b4.w };
    __syncthreads();
    #pragma unroll
    for (int i = 0; i < 4; i++)
        #pragma unroll
        for (int jj = 0; jj < 4; jj++)
            Cs[tx * 4 + jj][ty * 4 + i] = c[i][jj] + pb[jj];
    __syncthreads();

    float g0 = gamma[0];
    int b  = m0 >> 12;
    int n0 = m0 & 4095;
    for (int p = 0; p < 16; p++) {
        int jl = p * 4 + (tid >> 6);
        int nl = tid & 63;
        size_t gi = (size_t)(b * 256 + j0 + jl) * 4096 + n0 + nl;
        out[gi] = g0 * Cs[jl][nl] + x[gi];
    }
}

// ---------------- launch ----------------------------------------------------
extern "C" void kernel_launch(void* const* d_in, const int* in_sizes, int n_in,
                              void* d_out, int out_size)
{
    const float* x      = (const float*)d_in[0];
    const float* norm_w = (const float*)d_in[1];
    const float* norm_b = (const float*)d_in[2];
    const float* qkv_w  = (const float*)d_in[3];
    const float* qkv_b  = (const float*)d_in[4];
    const float* proj_w = (const float*)d_in[5];
    const float* proj_b = (const float*)d_in[6];
    const float* gamma  = (const float*)d_in[7];
    float* out = (float*)d_out;

    cudaFuncSetAttribute(attn_kernel, cudaFuncAttributeMaxDynamicSharedMemorySize,
                         (int)ATTN_SMEM_BYTES);

    ln_kernel<<<256, 256>>>(x, norm_w, norm_b);
    qkv_gemm_kernel<<<dim3(128, 12), 256>>>(qkv_w, qkv_b);
    attn_kernel<<<512, 256, ATTN_SMEM_BYTES>>>();
    proj_kernel<<<dim3(128, 4), 256>>>(proj_w, proj_b, gamma, x, out);
}

// round 6
// speedup vs baseline: 10.9891x; 10.9891x over previous
#include <cuda_runtime.h>

#define N_TOK 4096
#define CDIM  256

// bf16 data stored as raw 16-bit words (no cuda_bf16 dependency)
__device__ __align__(16) unsigned short g_xnb [2 * N_TOK * CDIM];
__device__ __align__(16) unsigned short g_qkvb[2 * N_TOK * 3 * CDIM];
__device__ __align__(16) unsigned short g_attb[2 * N_TOK * CDIM];
__device__ __align__(16) unsigned short g_wqkvb[3 * CDIM * CDIM];
__device__ __align__(16) unsigned short g_wprojb[CDIM * CDIM];

#define QSC (0.17677669529663689f * 1.4426950408889634f)

__device__ __forceinline__ float ex2f(float x) {
    float y;
    asm("ex2.approx.ftz.f32 %0, %1;" : "=f"(y) : "f"(x));
    return y;
}
__device__ __forceinline__ unsigned s2u(const void* p) {
    return (unsigned)__cvta_generic_to_shared(p);
}
__device__ __forceinline__ void ldsm4(unsigned& r0, unsigned& r1, unsigned& r2, unsigned& r3, unsigned a) {
    asm volatile("ldmatrix.sync.aligned.m8n8.x4.shared.b16 {%0,%1,%2,%3}, [%4];" : "=r"(r0), "=r"(r1), "=r"(r2), "=r"(r3) : "r"(a));
}
__device__ __forceinline__ void ldsm4t(unsigned& r0, unsigned& r1, unsigned& r2, unsigned& r3, unsigned a) {
    asm volatile("ldmatrix.sync.aligned.m8n8.x4.trans.shared.b16 {%0,%1,%2,%3}, [%4];" : "=r"(r0), "=r"(r1), "=r"(r2), "=r"(r3) : "r"(a));
}
__device__ __forceinline__ void mma16816(float* c, const unsigned* a, unsigned b0, unsigned b1) {
    asm volatile("mma.sync.aligned.m16n8k16.row.col.f32.bf16.bf16.f32 {%0,%1,%2,%3},{%4,%5,%6,%7},{%8,%9},{%0,%1,%2,%3};" : "+f"(c[0]), "+f"(c[1]), "+f"(c[2]), "+f"(c[3]) : "r"(a[0]), "r"(a[1]), "r"(a[2]), "r"(a[3]), "r"(b0), "r"(b1));
}
__device__ __forceinline__ unsigned pack_bf(float lo, float hi) {
    unsigned r;
    asm("cvt.rn.bf16x2.f32 %0, %1, %2;" : "=r"(r) : "f"(hi), "f"(lo));
    return r;
}

// Kernel 0: weight conversion fp32 -> packed bf16 pairs
__global__ __launch_bounds__(256) void convw_kernel(const float* __restrict__ qw, const float* __restrict__ pw)
{
    int i = blockIdx.x * 256 + threadIdx.x;
    if (i < 98304) {
        ((unsigned*)g_wqkvb)[i] = pack_bf(qw[2 * i], qw[2 * i + 1]);
    } else {
        int j = i - 98304;
        ((unsigned*)g_wprojb)[j] = pack_bf(pw[2 * j], pw[2 * j + 1]);
    }
}

// Kernel 1: LayerNorm + (B,C,N)->(B,N,C) transpose, bf16 out
__global__ __launch_bounds__(256) void ln_kernel(const float* __restrict__ x, const float* __restrict__ nw, const float* __restrict__ nb)
{
    __shared__ float ts[CDIM][33];
    int tid = threadIdx.x;
    int bb = blockIdx.x >> 7;
    int n0 = (blockIdx.x & 127) * 32;

    int j = tid & 31;
    for (int c = tid >> 5; c < CDIM; c += 8) {
        ts[c][j] = x[(size_t)(bb * CDIM + c) * N_TOK + n0 + j];
    }
    __syncthreads();

    int jt = tid >> 3;
    int g = tid & 7;
    float sum = 0.f;
    float sq = 0.f;
    #pragma unroll
    for (int c0 = 0; c0 < CDIM; c0 += 8) {
        float v = ts[c0 + g][jt];
        sum += v;
        sq += v * v;
    }
    #pragma unroll
    for (int mm = 1; mm < 8; mm <<= 1) {
        sum += __shfl_xor_sync(0xffffffffu, sum, mm);
        sq  += __shfl_xor_sync(0xffffffffu, sq, mm);
    }
    float mean = sum * (1.f / CDIM);
    float var = sq * (1.f / CDIM) - mean * mean;
    float rstd = rsqrtf(var + 1e-5f);

    unsigned short* orow = g_xnb + (size_t)(bb * N_TOK + n0 + jt) * CDIM;
    #pragma unroll
    for (int i = 0; i < 8; i++) {
        int c = g * 32 + i * 4;
        float4 w4 = *(const float4*)(nw + c);
        float4 b4 = *(const float4*)(nb + c);
        float o0 = (ts[c + 0][jt] - mean) * rstd * w4.x + b4.x;
        float o1 = (ts[c + 1][jt] - mean) * rstd * w4.y + b4.y;
        float o2 = (ts[c + 2][jt] - mean) * rstd * w4.z + b4.z;
        float o3 = (ts[c + 3][jt] - mean) * rstd * w4.w + b4.w;
        uint2 pk;
        pk.x = pack_bf(o0, o1);
        pk.y = pack_bf(o2, o3);
        *(uint2*)(orow + c) = pk;
    }
}

// Kernel 2: QKV GEMM bf16 (8192x768x256) + bias, q prescaled by QSC
__global__ __launch_bounds__(256) void qkv_gemm_kernel(const float* __restrict__ bias)
{
    __shared__ __align__(16) unsigned short As[2][128][40];
    __shared__ __align__(16) unsigned short Bs[2][64][40];
    int tid = threadIdx.x;
    int li = tid & 31;
    int wp = tid >> 5;
    int m0 = blockIdx.x * 128;
    int j0 = blockIdx.y * 64;
    int wm = (wp >> 1) * 32;
    int wn = (wp & 1) * 32;
    float c[2][4][4];
    #pragma unroll
    for (int a1 = 0; a1 < 2; a1++) {
        #pragma unroll
        for (int a2 = 0; a2 < 4; a2++) {
            #pragma unroll
            for (int a3 = 0; a3 < 4; a3++) {
                c[a1][a2][a3] = 0.f;
            }
        }
    }

    int ra = tid >> 2;
    int cg = tid & 3;
    *(uint4*)&As[0][ra][cg * 8] = *(const uint4*)(g_xnb + (size_t)(m0 + ra) * 256 + cg * 8);
    *(uint4*)&As[0][64 + ra][cg * 8] = *(const uint4*)(g_xnb + (size_t)(m0 + 64 + ra) * 256 + cg * 8);
    *(uint4*)&Bs[0][ra][cg * 8] = *(const uint4*)(g_wqkvb + (size_t)(j0 + ra) * 256 + cg * 8);
    __syncthreads();

    int pg = 0;
    for (int ck = 0; ck < 8; ck++) {
        uint4 na0;
        uint4 na1;
        uint4 nb0;
        int ok = (ck < 7) ? 1 : 0;
        if (ok) {
            int kc = (ck + 1) * 32;
            na0 = *(const uint4*)(g_xnb + (size_t)(m0 + ra) * 256 + kc + cg * 8);
            na1 = *(const uint4*)(g_xnb + (size_t)(m0 + 64 + ra) * 256 + kc + cg * 8);
            nb0 = *(const uint4*)(g_wqkvb + (size_t)(j0 + ra) * 256 + kc + cg * 8);
        }
        #pragma unroll
        for (int ks = 0; ks < 2; ks++) {
            unsigned a[2][4];
            #pragma unroll
            for (int mt = 0; mt < 2; mt++) {
                ldsm4(a[mt][0], a[mt][1], a[mt][2], a[mt][3], s2u(&As[pg][wm + mt * 16 + (li & 15)][ks * 16 + (li >> 4) * 8]));
            }
            #pragma unroll
            for (int np = 0; np < 2; np++) {
                unsigned r0, r1, r2, r3;
                ldsm4(r0, r1, r2, r3, s2u(&Bs[pg][wn + np * 16 + (li & 15)][ks * 16 + (li >> 4) * 8]));
                #pragma unroll
                for (int mt = 0; mt < 2; mt++) {
                    mma16816(c[mt][2 * np], a[mt], r0, r2);
                    mma16816(c[mt][2 * np + 1], a[mt], r1, r3);
                }
            }
        }
        if (ok) {
            *(uint4*)&As[pg ^ 1][ra][cg * 8] = na0;
            *(uint4*)&As[pg ^ 1][64 + ra][cg * 8] = na1;
            *(uint4*)&Bs[pg ^ 1][ra][cg * 8] = nb0;
        }
        __syncthreads();
        pg ^= 1;
    }

    #pragma unroll
    for (int mt = 0; mt < 2; mt++) {
        int r = m0 + wm + mt * 16 + (li >> 2);
        #pragma unroll
        for (int nt = 0; nt < 4; nt++) {
            int jc = j0 + wn + nt * 8 + (li & 3) * 2;
            float b0 = bias[jc];
            float b1 = bias[jc + 1];
            float s = (jc < 256) ? QSC : 1.0f;
            float v0 = (c[mt][nt][0] + b0) * s;
            float v1 = (c[mt][nt][1] + b1) * s;
            float v2 = (c[mt][nt][2] + b0) * s;
            float v3 = (c[mt][nt][3] + b1) * s;
            *(unsigned*)(g_qkvb + (size_t)r * 768 + jc) = pack_bf(v0, v1);
            *(unsigned*)(g_qkvb + (size_t)(r + 8) * 768 + jc) = pack_bf(v2, v3);
        }
    }
}

// Kernel 3: flash attention, bf16 MMA, online softmax in registers
__global__ __launch_bounds__(256) void attn_kernel()
{
    __shared__ __align__(16) unsigned short Qs[128][40];
    __shared__ __align__(16) unsigned short Ks[2][64][40];
    __shared__ __align__(16) unsigned short Vs[2][64][40];
    int tid = threadIdx.x;
    int li = tid & 31;
    int wp = tid >> 5;
    int bid = blockIdx.x;
    int bb = bid >> 8;
    int h = (bid >> 5) & 7;
    int q0 = (bid & 31) * 128;
    size_t bN = (size_t)bb * N_TOK;

    int rr = tid >> 2;
    int cg = tid & 3;
    *(uint4*)&Qs[rr][cg * 8] = *(const uint4*)(g_qkvb + (bN + q0 + rr) * 768 + h * 32 + cg * 8);
    *(uint4*)&Qs[64 + rr][cg * 8] = *(const uint4*)(g_qkvb + (bN + q0 + 64 + rr) * 768 + h * 32 + cg * 8);
    *(uint4*)&Ks[0][rr][cg * 8] = *(const uint4*)(g_qkvb + (bN + rr) * 768 + 256 + h * 32 + cg * 8);
    *(uint4*)&Vs[0][rr][cg * 8] = *(const uint4*)(g_qkvb + (bN + rr) * 768 + 512 + h * 32 + cg * 8);
    __syncthreads();

    unsigned qa[2][4];
    #pragma unroll
    for (int ks = 0; ks < 2; ks++) {
        ldsm4(qa[ks][0], qa[ks][1], qa[ks][2], qa[ks][3], s2u(&Qs[wp * 16 + (li & 15)][ks * 16 + (li >> 4) * 8]));
    }

    float oacc[4][4];
    #pragma unroll
    for (int a1 = 0; a1 < 4; a1++) {
        #pragma unroll
        for (int a2 = 0; a2 < 4; a2++) {
            oacc[a1][a2] = 0.f;
        }
    }
    float rm0 = -1e30f;
    float rm1 = -1e30f;
    float rl0 = 0.f;
    float rl1 = 0.f;

    for (int kt = 0; kt < 64; kt++) {
        int cb = kt & 1;
        uint4 kreg;
        uint4 vreg;
        int ok = (kt + 1 < 64) ? 1 : 0;
        if (ok) {
            size_t rowb = bN + (size_t)(kt + 1) * 64 + rr;
            kreg = *(const uint4*)(g_qkvb + rowb * 768 + 256 + h * 32 + cg * 8);
            vreg = *(const uint4*)(g_qkvb + rowb * 768 + 512 + h * 32 + cg * 8);
        }

        float sacc[8][4];
        #pragma unroll
        for (int nt = 0; nt < 8; nt++) {
            sacc[nt][0] = 0.f;
            sacc[nt][1] = 0.f;
            sacc[nt][2] = 0.f;
            sacc[nt][3] = 0.f;
        }
        #pragma unroll
        for (int np = 0; np < 4; np++) {
            unsigned r0, r1, r2, r3;
            ldsm4(r0, r1, r2, r3, s2u(&Ks[cb][np * 16 + (li & 15)][(li >> 4) * 8]));
            mma16816(sacc[2 * np], qa[0], r0, r2);
            mma16816(sacc[2 * np + 1], qa[0], r1, r3);
            ldsm4(r0, r1, r2, r3, s2u(&Ks[cb][np * 16 + (li & 15)][16 + (li >> 4) * 8]));
            mma16816(sacc[2 * np], qa[1], r0, r2);
            mma16816(sacc[2 * np + 1], qa[1], r1, r3);
        }

        float tm0 = -1e30f;
        float tm1 = -1e30f;
        #pragma unroll
        for (int nt = 0; nt < 8; nt++) {
            tm0 = fmaxf(tm0, fmaxf(sacc[nt][0], sacc[nt][1]));
            tm1 = fmaxf(tm1, fmaxf(sacc[nt][2], sacc[nt][3]));
        }
        tm0 = fmaxf(tm0, __shfl_xor_sync(0xffffffffu, tm0, 1));
        tm0 = fmaxf(tm0, __shfl_xor_sync(0xffffffffu, tm0, 2));
        tm1 = fmaxf(tm1, __shfl_xor_sync(0xffffffffu, tm1, 1));
        tm1 = fmaxf(tm1, __shfl_xor_sync(0xffffffffu, tm1, 2));
        float mn0 = fmaxf(rm0, tm0);
        float mn1 = fmaxf(rm1, tm1);
        float co0 = ex2f(rm0 - mn0);
        float co1 = ex2f(rm1 - mn1);
        rm0 = mn0;
        rm1 = mn1;
        float rs0 = 0.f;
        float rs1 = 0.f;
        #pragma unroll
        for (int nt = 0; nt < 8; nt++) {
            sacc[nt][0] = ex2f(sacc[nt][0] - mn0);
            sacc[nt][1] = ex2f(sacc[nt][1] - mn0);
            sacc[nt][2] = ex2f(sacc[nt][2] - mn1);
            sacc[nt][3] = ex2f(sacc[nt][3] - mn1);
            rs0 += sacc[nt][0] + sacc[nt][1];
            rs1 += sacc[nt][2] + sacc[nt][3];
        }
        rs0 += __shfl_xor_sync(0xffffffffu, rs0, 1);
        rs0 += __shfl_xor_sync(0xffffffffu, rs0, 2);
        rs1 += __shfl_xor_sync(0xffffffffu, rs1, 1);
        rs1 += __shfl_xor_sync(0xffffffffu, rs1, 2);
        rl0 = rl0 * co0 + rs0;
        rl1 = rl1 * co1 + rs1;
        #pragma unroll
        for (int nt = 0; nt < 4; nt++) {
            oacc[nt][0] *= co0;
            oacc[nt][1] *= co0;
            oacc[nt][2] *= co1;
            oacc[nt][3] *= co1;
        }

        #pragma unroll
        for (int j = 0; j < 4; j++) {
            unsigned pa[4];
            pa[0] = pack_bf(sacc[2 * j][0], sacc[2 * j][1]);
            pa[1] = pack_bf(sacc[2 * j][2], sacc[2 * j][3]);
            pa[2] = pack_bf(sacc[2 * j + 1][0], sacc[2 * j + 1][1]);
            pa[3] = pack_bf(sacc[2 * j + 1][2], sacc[2 * j + 1][3]);
            unsigned r0, r1, r2, r3;
            ldsm4t(r0, r1, r2, r3, s2u(&Vs[cb][j * 16 + (li & 15)][(li >> 4) * 8]));
            mma16816(oacc[0], pa, r0, r1);
            mma16816(oacc[1], pa, r2, r3);
            ldsm4t(r0, r1, r2, r3, s2u(&Vs[cb][j * 16 + (li & 15)][16 + (li >> 4) * 8]));
            mma16816(oacc[2], pa, r0, r1);
            mma16816(oacc[3], pa, r2, r3);
        }

        if (ok) {
            *(uint4*)&Ks[cb ^ 1][rr][cg * 8] = kreg;
            *(uint4*)&Vs[cb ^ 1][rr][cg * 8] = vreg;
        }
        __syncthreads();
    }

    float inv0 = 1.0f / rl0;
    float inv1 = 1.0f / rl1;
    int rg = q0 + wp * 16 + (li >> 2);
    #pragma unroll
    for (int nt = 0; nt < 4; nt++) {
        int col = h * 32 + nt * 8 + (li & 3) * 2;
        *(unsigned*)(g_attb + (bN + rg) * 256 + col) = pack_bf(oacc[nt][0] * inv0, oacc[nt][1] * inv0);
        *(unsigned*)(g_attb + (bN + rg + 8) * 256 + col) = pack_bf(oacc[nt][2] * inv1, oacc[nt][3] * inv1);
    }
}

// Kernel 4: proj GEMM bf16 + gamma residual, (B,N,C)->(B,C,N) via smem
#define PROJ_SMEM_BYTES 33024

__global__ __launch_bounds__(256) void proj_kernel(const float* __restrict__ bias, const float* __restrict__ gamma, const float* __restrict__ x, float* __restrict__ out)
{
    __shared__ __align__(16) char smraw[PROJ_SMEM_BYTES];
    unsigned short (*As)[128][40] = (unsigned short (*)[128][40])(smraw);
    unsigned short (*Bs)[64][40] = (unsigned short (*)[64][40])(smraw + 20480);
    float (*Cs)[129] = (float (*)[129])(smraw);

    int tid = threadIdx.x;
    int li = tid & 31;
    int wp = tid >> 5;
    int m0 = blockIdx.x * 128;
    int j0 = blockIdx.y * 64;
    int wm = (wp >> 1) * 32;
    int wn = (wp & 1) * 32;
    float c[2][4][4];
    #pragma unroll
    for (int a1 = 0; a1 < 2; a1++) {
        #pragma unroll
        for (int a2 = 0; a2 < 4; a2++) {
            #pragma unroll
            for (int a3 = 0; a3 < 4; a3++) {
                c[a1][a2][a3] = 0.f;
            }
        }
    }
    int ra = tid >> 2;
    int cg = tid & 3;

    *(uint4*)&As[0][ra][cg * 8] = *(const uint4*)(g_attb + (size_t)(m0 + ra) * 256 + cg * 8);
    *(uint4*)&As[0][64 + ra][cg * 8] = *(const uint4*)(g_attb + (size_t)(m0 + 64 + ra) * 256 + cg * 8);
    *(uint4*)&Bs[0][ra][cg * 8] = *(const uint4*)(g_wprojb + (size_t)(j0 + ra) * 256 + cg * 8);
    __syncthreads();

    int pg = 0;
    for (int ck = 0; ck < 8; ck++) {
        uint4 na0;
        uint4 na1;
        uint4 nb0;
        int ok = (ck < 7) ? 1 : 0;
        if (ok) {
            int kc = (ck + 1) * 32;
            na0 = *(const uint4*)(g_attb + (size_t)(m0 + ra) * 256 + kc + cg * 8);
            na1 = *(const uint4*)(g_attb + (size_t)(m0 + 64 + ra) * 256 + kc + cg * 8);
            nb0 = *(const uint4*)(g_wprojb + (size_t)(j0 + ra) * 256 + kc + cg * 8);
        }
        #pragma unroll
        for (int ks = 0; ks < 2; ks++) {
            unsigned a[2][4];
            #pragma unroll
            for (int mt = 0; mt < 2; mt++) {
                ldsm4(a[mt][0], a[mt][1], a[mt][2], a[mt][3], s2u(&As[pg][wm + mt * 16 + (li & 15)][ks * 16 + (li >> 4) * 8]));
            }
            #pragma unroll
            for (int np = 0; np < 2; np++) {
                unsigned r0, r1, r2, r3;
                ldsm4(r0, r1, r2, r3, s2u(&Bs[pg][wn + np * 16 + (li & 15)][ks * 16 + (li >> 4) * 8]));
                #pragma unroll
                for (int mt = 0; mt < 2; mt++) {
                    mma16816(c[mt][2 * np], a[mt], r0, r2);
                    mma16816(c[mt][2 * np + 1], a[mt], r1, r3);
                }
            }
        }
        if (ok) {
            *(uint4*)&As[pg ^ 1][ra][cg * 8] = na0;
            *(uint4*)&As[pg ^ 1][64 + ra][cg * 8] = na1;
            *(uint4*)&Bs[pg ^ 1][ra][cg * 8] = nb0;
        }
        __syncthreads();
        pg ^= 1;
    }

    __syncthreads();
    #pragma unroll
    for (int mt = 0; mt < 2; mt++) {
        int rl = wm + mt * 16 + (li >> 2);
        #pragma unroll
        for (int nt = 0; nt < 4; nt++) {
            int cl = wn + nt * 8 + (li & 3) * 2;
            float b0 = bias[j0 + cl];
            float b1 = bias[j0 + cl + 1];
            Cs[cl][rl] = c[mt][nt][0] + b0;
            Cs[cl + 1][rl] = c[mt][nt][1] + b1;
            Cs[cl][rl + 8] = c[mt][nt][2] + b0;
            Cs[cl + 1][rl + 8] = c[mt][nt][3] + b1;
        }
    }
    __syncthreads();

    float g0 = gamma[0];
    int bb = m0 >> 12;
    int n0 = m0 & 4095;
    #pragma unroll
    for (int p = 0; p < 32; p++) {
        int idx = p * 256 + tid;
        int cl = idx >> 7;
        int rl = idx & 127;
        size_t gi = (size_t)(bb * 256 + j0 + cl) * 4096 + n0 + rl;
        out[gi] = g0 * Cs[cl][rl] + x[gi];
    }
}

extern "C" void kernel_launch(void* const* d_in, const int* in_sizes, int n_in, void* d_out, int out_size)
{
    const float* x = (const float*)d_in[0];
    const float* norm_w = (const float*)d_in[1];
    const float* norm_b = (const float*)d_in[2];
    const float* qkv_w = (const float*)d_in[3];
    const float* qkv_b = (const float*)d_in[4];
    const float* proj_w = (const float*)d_in[5];
    const float* proj_b = (const float*)d_in[6];
    const float* gamma = (const float*)d_in[7];
    float* out = (float*)d_out;

    convw_kernel<<<512, 256>>>(qkv_w, proj_w);
    ln_kernel<<<256, 256>>>(x, norm_w, norm_b);
    qkv_gemm_kernel<<<dim3(64, 12), 256>>>(qkv_b);
    attn_kernel<<<512, 256>>>();
    proj_kernel<<<dim3(64, 4), 256>>>(proj_b, gamma, x, out);
}